// round 6
// baseline (speedup 1.0000x reference)
#include <cuda_runtime.h>
#include <math.h>

// Problem constants
#define BB 8
#define CC 256
#define HH 128
#define WW 128
#define HP 64
#define WP 64
#define NC8 32
#define CE  240   // enhanced output channels of fused conv
#define FIN 496   // fused conv input channels (240 bev + 256 T)

// -------- scratch (device globals; no allocation allowed) --------
__device__ float g_A[3][BB][CC][WW];          // A0=S-x_bot, A1=S, A2=S-x_top
__device__ float g_bevpool[BB][CC][HP][WP];   // avgpool2(bev_x)
__device__ float g_k[BB][NC8][WP];
__device__ float g_kq[BB][CC][WP];
__device__ float g_kqb[BB][WP];
__device__ float g_e[BB][HP][WP];             // energy, then normalized in-place
__device__ float g_vs[BB][CC][WP];            // vsum
__device__ float g_G[BB][CE][9][WP];          // fw2 (x) vs

// packed f32x2 helpers
__device__ __forceinline__ void ffma2(unsigned long long& d, unsigned long long a,
                                      unsigned long long b) {
    asm("fma.rn.f32x2 %0, %1, %2, %0;" : "+l"(d) : "l"(a), "l"(b));
}
__device__ __forceinline__ unsigned long long pack2(float lo, float hi) {
    unsigned long long r;
    asm("mov.b64 %0, {%1, %2};" : "=l"(r) : "f"(lo), "f"(hi));
    return r;
}
__device__ __forceinline__ float2 unpack2(unsigned long long v) {
    float2 r;
    asm("mov.b64 {%0, %1}, %2;" : "=f"(r.x), "=f"(r.y) : "l"(v));
    return r;
}

// ---------------------------------------------------------------
// K1: column sums of front_x + first/last row corrections
__global__ void front_reduce_kernel(const float* __restrict__ fx) {
    int c = blockIdx.x, b = blockIdx.y, w = threadIdx.x;
    const float* p = fx + (((size_t)b * CC + c) * HH) * WW + w;
    float x0 = p[0];
    float xN = p[127 * WW];
    float s = 0.f;
#pragma unroll 8
    for (int h = 0; h < HH; h++) s += p[h * WW];
    g_A[0][b][c][w] = s - xN;
    g_A[1][b][c][w] = s;
    g_A[2][b][c][w] = s - x0;
}

// K2: 2x2 avgpool of bev_x
__global__ void bevpool_kernel(const float* __restrict__ bev) {
    int idx = blockIdx.x * 256 + threadIdx.x;
    int w  = idx & 63;
    int h  = (idx >> 6) & 63;
    int bc = idx >> 12;
    const float2* r0 = (const float2*)(bev + ((size_t)bc * HH + 2 * h) * WW);
    const float2* r1 = (const float2*)(bev + ((size_t)bc * HH + 2 * h + 1) * WW);
    float2 a = r0[w], d = r1[w];
    ((float*)g_bevpool)[idx] = 0.25f * (a.x + a.y + d.x + d.y);
}

// K3
__global__ void k_kernel(const float* __restrict__ kw, const float* __restrict__ kb) {
    int tid = blockIdx.x * 256 + threadIdx.x;
    int w = tid & 63, o = (tid >> 6) & 31, b = tid >> 11;
    float acc = 0.f;
#pragma unroll 4
    for (int c = 0; c < CC; c++) {
        float m = (g_A[1][b][c][2 * w] + g_A[1][b][c][2 * w + 1]) * (1.f / 256.f);
        acc += kw[o * CC + c] * m;
    }
    g_k[b][o][w] = acc + kb[o];
}

// K4
__global__ void kq_kernel(const float* __restrict__ qw, const float* __restrict__ qb) {
    int tid = blockIdx.x * 256 + threadIdx.x;
    int w = tid & 63, c = (tid >> 6) & 255, b = tid >> 14;
    float acc = 0.f, accb = 0.f;
#pragma unroll 8
    for (int o = 0; o < NC8; o++) {
        float kk = g_k[b][o][w];
        acc  += kk * qw[o * CC + c];
        accb += kk * qb[o];
    }
    g_kq[b][c][w] = acc;
    if (c == 0) g_kqb[b][w] = accb;
}

// K5
__global__ void e_kernel() {
    int w = threadIdx.x, h = blockIdx.x, b = blockIdx.y;
    float acc = g_kqb[b][w];
#pragma unroll 4
    for (int c = 0; c < CC; c++)
        acc += g_kq[b][c][w] * g_bevpool[b][c][h][w];
    g_e[b][h][w] = acc;
}

// K6
__global__ void enorm_kernel() {
    int w = blockIdx.x, b = blockIdx.y, h = threadIdx.x;
    float v = g_e[b][h][w];
    float s = v * v;
#pragma unroll
    for (int off = 16; off; off >>= 1) s += __shfl_xor_sync(0xffffffffu, s, off);
    __shared__ float sh[2];
    if ((h & 31) == 0) sh[h >> 5] = s;
    __syncthreads();
    float tot = sh[0] + sh[1];
    g_e[b][h][w] = v * rsqrtf(tot);
}

// K7
__global__ void vsum_kernel(const float* __restrict__ vw, const float* __restrict__ vb) {
    __shared__ float sA[3][132];
    __shared__ float sW[8][9];
    int b = blockIdx.y, cg = blockIdx.x;
    int t = threadIdx.x;
    float acc[8];
#pragma unroll
    for (int j = 0; j < 8; j++) acc[j] = 0.f;

    for (int ci = 0; ci < CC; ci++) {
        __syncthreads();
        for (int i = t; i < 3 * 130; i += 64) {
            int arr = i / 130, u = i % 130;
            float v = 0.f;
            if (u >= 1 && u <= 128) v = g_A[arr][b][ci][u - 1];
            sA[arr][u] = v;
        }
        for (int i = t; i < 72; i += 64) {
            int j = i / 9, kk = i % 9;
            sW[j][kk] = vw[((size_t)(cg * 8 + j) * CC + ci) * 9 + kk];
        }
        __syncthreads();
#pragma unroll
        for (int sub = 0; sub < 2; sub++) {
            int wf = 2 * t + sub;
            float a[3][3];
#pragma unroll
            for (int dy = 0; dy < 3; dy++)
#pragma unroll
                for (int dx = 0; dx < 3; dx++) a[dy][dx] = sA[dy][wf + dx];
#pragma unroll
            for (int j = 0; j < 8; j++) {
                float s = acc[j];
#pragma unroll
                for (int dy = 0; dy < 3; dy++)
#pragma unroll
                    for (int dx = 0; dx < 3; dx++) s += sW[j][dy * 3 + dx] * a[dy][dx];
                acc[j] = s;
            }
        }
    }
#pragma unroll
    for (int j = 0; j < 8; j++)
        g_vs[b][cg * 8 + j][t] = 0.25f * acc[j] + 64.f * vb[cg * 8 + j];
}

// K8
__global__ void G_kernel(const float* __restrict__ fw) {
    int b = blockIdx.y, o = blockIdx.x, t = threadIdx.x;
    float acc[9];
#pragma unroll
    for (int j = 0; j < 9; j++) acc[j] = 0.f;
    for (int c = 0; c < CC; c++) {
        float v = g_vs[b][c][t];
        const float* wp = fw + ((size_t)o * FIN + 240 + c) * 9;
#pragma unroll
        for (int j = 0; j < 9; j++) acc[j] += wp[j] * v;
    }
#pragma unroll
    for (int j = 0; j < 9; j++) g_G[b][o][j][t] = acc[j];
}

// K9
__global__ void copy16_kernel(const float* __restrict__ bev, float* __restrict__ out) {
    int idx = blockIdx.x * 256 + threadIdx.x;
    int b = idx / (16 * 4096);
    int r = idx - b * (16 * 4096);
    size_t off = (size_t)b * (CC * 4096) + r;
    ((float4*)out)[off] = ((const float4*)bev)[off];
}

// K10: fused 3x3 conv on bev_x[:,16:] + factorized T epilogue, packed f32x2 math.
// Tile 16(y) x 32(x). Block 256: 4 o-groups x 64 threads (8y x 8x).
// Thread: 4 out-ch x (2y x 4x) pixels = two x-pairs per row, packed.
// grid (32 xy-tiles, 15 o-tiles, BB)
#define CIB 4
__global__ void __launch_bounds__(256, 2)
fused_conv_kernel(const float* __restrict__ bev, const float* __restrict__ fw,
                  const float* __restrict__ fb, float* __restrict__ out) {
    __shared__ float  s_in[CIB][18][36];   // halo tile 18x34, padded to 36
    __shared__ float2 s_w2[CIB][16][9];    // duplicated weights (w,w)

    int b  = blockIdx.z;
    int ot = blockIdx.y;                   // 0..14
    int xt = blockIdx.x & 3, yt = blockIdx.x >> 2;
    int x0 = xt * 32, y0 = yt * 16;

    int t  = threadIdx.x;
    int og = t >> 6;                       // 0..3 (warp-uniform)
    int r  = t & 63;
    int py = r >> 3, px = r & 7;
    int yb = 2 * py, xb = 4 * px;          // thread pixel base inside tile

    unsigned long long acc2[4][2][2];      // [oi][sy][xpair]
#pragma unroll
    for (int i = 0; i < 4; i++)
#pragma unroll
        for (int j = 0; j < 2; j++) { acc2[i][j][0] = 0ull; acc2[i][j][1] = 0ull; }

    const float* bevb = bev + (size_t)b * CC * (HH * WW);

    for (int cb = 0; cb < 240; cb += CIB) {
        __syncthreads();
        // load CIB halo planes (18x34) into smem
        for (int i = t; i < CIB * 18 * 34; i += 256) {
            int ci4 = i / (18 * 34);
            int rem = i - ci4 * (18 * 34);
            int iy = rem / 34, ix = rem - iy * 34;
            int gy = y0 + iy - 1, gx = x0 + ix - 1;
            float v = 0.f;
            if ((unsigned)gy < 128u && (unsigned)gx < 128u)
                v = bevb[(size_t)(16 + cb + ci4) * (HH * WW) + gy * WW + gx];
            s_in[ci4][iy][ix] = v;
        }
        // load + duplicate CIB x 16 x 9 weights
        for (int i = t; i < CIB * 144; i += 256) {
            int ci4 = i / 144;
            int rr = i - ci4 * 144;
            int ow = rr / 9, kk = rr - ow * 9;
            float w = fw[((size_t)(ot * 16 + ow) * FIN + cb + ci4) * 9 + kk];
            s_w2[ci4][ow][kk] = make_float2(w, w);
        }
        __syncthreads();

#pragma unroll
        for (int ci4 = 0; ci4 < CIB; ci4++) {
            // build 5 overlapping input pairs per row: P[j]=(in[j],in[j+1]), j=0..4
            unsigned long long P[4][5];
#pragma unroll
            for (int iy = 0; iy < 4; iy++) {
                const float* row = &s_in[ci4][yb + iy][xb];  // 8B-aligned (xb%4==0, stride 36 even)
                float2 v01 = *(const float2*)(row);
                float2 v23 = *(const float2*)(row + 2);
                float2 v45 = *(const float2*)(row + 4);
                P[iy][0] = pack2(v01.x, v01.y);
                P[iy][1] = pack2(v01.y, v23.x);
                P[iy][2] = pack2(v23.x, v23.y);
                P[iy][3] = pack2(v23.y, v45.x);
                P[iy][4] = pack2(v45.x, v45.y);
            }
#pragma unroll
            for (int oi = 0; oi < 4; oi++) {
                const unsigned long long* w2 =
                    (const unsigned long long*)&s_w2[ci4][og * 4 + oi][0];
                unsigned long long wk[9];
#pragma unroll
                for (int j = 0; j < 9; j++) wk[j] = w2[j];  // warp-broadcast LDS.64
#pragma unroll
                for (int sy = 0; sy < 2; sy++) {
#pragma unroll
                    for (int dy = 0; dy < 3; dy++) {
#pragma unroll
                        for (int dx = 0; dx < 3; dx++) {
                            ffma2(acc2[oi][sy][0], wk[dy * 3 + dx], P[sy + dy][dx]);
                            ffma2(acc2[oi][sy][1], wk[dy * 3 + dx], P[sy + dy][dx + 2]);
                        }
                    }
                }
            }
        }
    }

    // Epilogue: bias + factorized T contribution, vectorized store
#pragma unroll
    for (int oi = 0; oi < 4; oi++) {
        int o = ot * 16 + og * 4 + oi;
        float bias = fb[o];
#pragma unroll
        for (int sy = 0; sy < 2; sy++) {
            int y = y0 + yb + sy;
            float2 pa = unpack2(acc2[oi][sy][0]);
            float2 pb = unpack2(acc2[oi][sy][1]);
            float vv[4] = { pa.x, pa.y, pb.x, pb.y };
            float4 res;
            float* rp = (float*)&res;
#pragma unroll
            for (int sx = 0; sx < 4; sx++) {
                int x = x0 + xb + sx;
                float v = vv[sx] + bias;
#pragma unroll
                for (int dy = 0; dy < 3; dy++) {
                    int yy = y + dy - 1;
                    if ((unsigned)yy >= 128u) continue;
                    int hh = yy >> 1;
#pragma unroll
                    for (int dx = 0; dx < 3; dx++) {
                        int xx = x + dx - 1;
                        if ((unsigned)xx >= 128u) continue;
                        int ww = xx >> 1;
                        v += g_e[b][hh][ww] * g_G[b][o][dy * 3 + dx][ww];
                    }
                }
                rp[sx] = v;
            }
            *(float4*)&out[((size_t)(b * CC + 16 + o) * HH + y) * WW + x0 + xb] = res;
        }
    }
}

// ---------------------------------------------------------------
extern "C" void kernel_launch(void* const* d_in, const int* in_sizes, int n_in,
                              void* d_out, int out_size) {
    const float* front = (const float*)d_in[0];
    const float* bev   = (const float*)d_in[1];
    const float* qw    = (const float*)d_in[2];
    const float* qb    = (const float*)d_in[3];
    const float* kw    = (const float*)d_in[4];
    const float* kb    = (const float*)d_in[5];
    const float* vw    = (const float*)d_in[6];
    const float* vb    = (const float*)d_in[7];
    const float* fw    = (const float*)d_in[8];
    const float* fb    = (const float*)d_in[9];
    float* out = (float*)d_out;

    front_reduce_kernel<<<dim3(CC, BB), 128>>>(front);
    bevpool_kernel<<<(BB * CC * HP * WP) / 256, 256>>>(bev);
    k_kernel<<<64, 256>>>(kw, kb);
    kq_kernel<<<512, 256>>>(qw, qb);
    e_kernel<<<dim3(HP, BB), WP>>>();
    enorm_kernel<<<dim3(WP, BB), HP>>>();
    vsum_kernel<<<dim3(32, BB), 64>>>(vw, vb);
    G_kernel<<<dim3(CE, BB), 64>>>(fw);
    copy16_kernel<<<2048, 256>>>(bev, out);
    fused_conv_kernel<<<dim3(32, 15, BB), 256>>>(bev, fw, fb, out);
}

// round 8
// speedup vs baseline: 1.3940x; 1.3940x over previous
#include <cuda_runtime.h>
#include <cuda_bf16.h>
#include <math.h>
#include <stdint.h>

// Problem constants
#define BB 8
#define CC 256
#define HH 128
#define WW 128
#define HP 64
#define WP 64
#define NC8 32
#define CE  240
#define FIN 496

// -------- scratch (device globals; no allocation allowed) --------
__device__ float g_A[3][BB][CC][WW];
__device__ float g_bevpool[BB][CC][HP][WP];
__device__ float g_k[BB][NC8][WP];
__device__ float g_kq[BB][CC][WP];
__device__ float g_kqb[BB][WP];
__device__ float g_e[BB][HP][WP];
__device__ float g_vs[BB][CC][WP];
__device__ float g_G[BB][CE][9][WP];

// channel-last bf16 hi/lo input planes: [b][y][x][ci(256)] ; 32 uint4 per pixel
__device__ uint4 g_Xh4[(size_t)BB * 128 * 128 * 32];
__device__ uint4 g_Xl4[(size_t)BB * 128 * 128 * 32];
// weight tiles: 36 (9 shifts x 4 ci-blocks) x [n=256][k=64] bf16, plain row-major
__device__ uint4 g_Wh4[36 * 2048];
__device__ uint4 g_Wl4[36 * 2048];

// ================= helpers =================
__device__ __forceinline__ uint32_t smem_to_u32(const void* p) {
    uint32_t a;
    asm("{ .reg .u64 t; cvta.to.shared.u64 t, %1; cvt.u32.u64 %0, t; }" : "=r"(a) : "l"(p));
    return a;
}
__device__ __forceinline__ void ldsm4(uint32_t* r, uint32_t addr) {
    asm volatile("ldmatrix.sync.aligned.m8n8.x4.shared.b16 {%0,%1,%2,%3}, [%4];"
                 : "=r"(r[0]), "=r"(r[1]), "=r"(r[2]), "=r"(r[3]) : "r"(addr));
}
__device__ __forceinline__ void mma_bf16(float* c, const uint32_t* a, const uint32_t* b) {
    asm volatile(
        "mma.sync.aligned.m16n8k16.row.col.f32.bf16.bf16.f32 "
        "{%0,%1,%2,%3}, {%4,%5,%6,%7}, {%8,%9}, {%0,%1,%2,%3};"
        : "+f"(c[0]), "+f"(c[1]), "+f"(c[2]), "+f"(c[3])
        : "r"(a[0]), "r"(a[1]), "r"(a[2]), "r"(a[3]), "r"(b[0]), "r"(b[1]));
}
__device__ __forceinline__ void cpasync16(uint32_t dst, const void* src, uint32_t sz) {
    asm volatile("cp.async.cg.shared.global [%0], [%1], 16, %2;"
                 :: "r"(dst), "l"(src), "r"(sz) : "memory");
}
#define CP_COMMIT() asm volatile("cp.async.commit_group;" ::: "memory")
#define CP_WAIT0()  asm volatile("cp.async.wait_group 0;" ::: "memory")

// ================= small kernels (validated in R3) =================
__global__ void front_reduce_kernel(const float* __restrict__ fx) {
    int c = blockIdx.x, b = blockIdx.y, w = threadIdx.x;
    const float* p = fx + (((size_t)b * CC + c) * HH) * WW + w;
    float x0 = p[0];
    float xN = p[127 * WW];
    float s = 0.f;
#pragma unroll 8
    for (int h = 0; h < HH; h++) s += p[h * WW];
    g_A[0][b][c][w] = s - xN;
    g_A[1][b][c][w] = s;
    g_A[2][b][c][w] = s - x0;
}

__global__ void bevpool_kernel(const float* __restrict__ bev) {
    int idx = blockIdx.x * 256 + threadIdx.x;
    int w  = idx & 63;
    int h  = (idx >> 6) & 63;
    int bc = idx >> 12;
    const float2* r0 = (const float2*)(bev + ((size_t)bc * HH + 2 * h) * WW);
    const float2* r1 = (const float2*)(bev + ((size_t)bc * HH + 2 * h + 1) * WW);
    float2 a = r0[w], d = r1[w];
    ((float*)g_bevpool)[idx] = 0.25f * (a.x + a.y + d.x + d.y);
}

__global__ void k_kernel(const float* __restrict__ kw, const float* __restrict__ kb) {
    int tid = blockIdx.x * 256 + threadIdx.x;
    int w = tid & 63, o = (tid >> 6) & 31, b = tid >> 11;
    float acc = 0.f;
#pragma unroll 4
    for (int c = 0; c < CC; c++) {
        float m = (g_A[1][b][c][2 * w] + g_A[1][b][c][2 * w + 1]) * (1.f / 256.f);
        acc += kw[o * CC + c] * m;
    }
    g_k[b][o][w] = acc + kb[o];
}

__global__ void kq_kernel(const float* __restrict__ qw, const float* __restrict__ qb) {
    int tid = blockIdx.x * 256 + threadIdx.x;
    int w = tid & 63, c = (tid >> 6) & 255, b = tid >> 14;
    float acc = 0.f, accb = 0.f;
#pragma unroll 8
    for (int o = 0; o < NC8; o++) {
        float kk = g_k[b][o][w];
        acc  += kk * qw[o * CC + c];
        accb += kk * qb[o];
    }
    g_kq[b][c][w] = acc;
    if (c == 0) g_kqb[b][w] = accb;
}

__global__ void e_kernel() {
    int w = threadIdx.x, h = blockIdx.x, b = blockIdx.y;
    float acc = g_kqb[b][w];
#pragma unroll 4
    for (int c = 0; c < CC; c++)
        acc += g_kq[b][c][w] * g_bevpool[b][c][h][w];
    g_e[b][h][w] = acc;
}

__global__ void enorm_kernel() {
    int w = blockIdx.x, b = blockIdx.y, h = threadIdx.x;
    float v = g_e[b][h][w];
    float s = v * v;
#pragma unroll
    for (int off = 16; off; off >>= 1) s += __shfl_xor_sync(0xffffffffu, s, off);
    __shared__ float sh[2];
    if ((h & 31) == 0) sh[h >> 5] = s;
    __syncthreads();
    float tot = sh[0] + sh[1];
    g_e[b][h][w] = v * rsqrtf(tot);
}

__global__ void vsum_kernel(const float* __restrict__ vw, const float* __restrict__ vb) {
    __shared__ float sA[3][132];
    __shared__ float sW[8][9];
    int b = blockIdx.y, cg = blockIdx.x;
    int t = threadIdx.x;
    float acc[8];
#pragma unroll
    for (int j = 0; j < 8; j++) acc[j] = 0.f;

    for (int ci = 0; ci < CC; ci++) {
        __syncthreads();
        for (int i = t; i < 3 * 130; i += 64) {
            int arr = i / 130, u = i % 130;
            float v = 0.f;
            if (u >= 1 && u <= 128) v = g_A[arr][b][ci][u - 1];
            sA[arr][u] = v;
        }
        for (int i = t; i < 72; i += 64) {
            int j = i / 9, kk = i % 9;
            sW[j][kk] = vw[((size_t)(cg * 8 + j) * CC + ci) * 9 + kk];
        }
        __syncthreads();
#pragma unroll
        for (int sub = 0; sub < 2; sub++) {
            int wf = 2 * t + sub;
            float a[3][3];
#pragma unroll
            for (int dy = 0; dy < 3; dy++)
#pragma unroll
                for (int dx = 0; dx < 3; dx++) a[dy][dx] = sA[dy][wf + dx];
#pragma unroll
            for (int j = 0; j < 8; j++) {
                float s = acc[j];
#pragma unroll
                for (int dy = 0; dy < 3; dy++)
#pragma unroll
                    for (int dx = 0; dx < 3; dx++) s += sW[j][dy * 3 + dx] * a[dy][dx];
                acc[j] = s;
            }
        }
    }
#pragma unroll
    for (int j = 0; j < 8; j++)
        g_vs[b][cg * 8 + j][t] = 0.25f * acc[j] + 64.f * vb[cg * 8 + j];
}

__global__ void G_kernel(const float* __restrict__ fw) {
    int b = blockIdx.y, o = blockIdx.x, t = threadIdx.x;
    float acc[9];
#pragma unroll
    for (int j = 0; j < 9; j++) acc[j] = 0.f;
    for (int c = 0; c < CC; c++) {
        float v = g_vs[b][c][t];
        const float* wp = fw + ((size_t)o * FIN + 240 + c) * 9;
#pragma unroll
        for (int j = 0; j < 9; j++) acc[j] += wp[j] * v;
    }
#pragma unroll
    for (int j = 0; j < 9; j++) g_G[b][o][j][t] = acc[j];
}

__global__ void copy16_kernel(const float* __restrict__ bev, float* __restrict__ out) {
    int idx = blockIdx.x * 256 + threadIdx.x;
    int b = idx / (16 * 4096);
    int r = idx - b * (16 * 4096);
    size_t off = (size_t)b * (CC * 4096) + r;
    ((float4*)out)[off] = ((const float4*)bev)[off];
}

// ================= precompute kernels =================
// Split bev[:,16:] into channel-last bf16 hi/lo planes (ci padded to 256 with zeros).
__global__ void __launch_bounds__(256) split_kernel(const float* __restrict__ bev) {
    __shared__ float sb[64][129];
    int y = blockIdx.x, b = blockIdx.y, t = threadIdx.x;
    for (int cb = 0; cb < 4; cb++) {
        __syncthreads();
        for (int i = t; i < 64 * 128; i += 256) {
            int ci = i >> 7, x = i & 127;
            int ch = cb * 64 + ci;
            float v = 0.f;
            if (ch < 240)
                v = bev[(((size_t)b * CC + 16 + ch) * HH + y) * WW + x];
            sb[ci][x] = v;
        }
        __syncthreads();
        for (int i = t; i < 128 * 32; i += 256) {
            int x = i >> 5, cp = i & 31;
            float v0 = sb[2 * cp][x], v1 = sb[2 * cp + 1][x];
            __nv_bfloat16 h0 = __float2bfloat16(v0);
            __nv_bfloat16 h1 = __float2bfloat16(v1);
            __nv_bfloat16 l0 = __float2bfloat16(v0 - __bfloat162float(h0));
            __nv_bfloat16 l1 = __float2bfloat16(v1 - __bfloat162float(h1));
            uint32_t hp = ((uint32_t)__bfloat16_as_ushort(h1) << 16) | __bfloat16_as_ushort(h0);
            uint32_t lp = ((uint32_t)__bfloat16_as_ushort(l1) << 16) | __bfloat16_as_ushort(l0);
            size_t base = (((size_t)b * 128 + y) * 128 + x) * 128 + cb * 32 + cp;
            ((uint32_t*)g_Xh4)[base] = hp;
            ((uint32_t*)g_Xl4)[base] = lp;
        }
    }
}

// Weight tiles: tile (s, cib) = [n=256][k=64] bf16 row-major. grid (64, 36)
__global__ void wbuild_kernel(const float* __restrict__ fw) {
    int tile = blockIdx.y;
    int s = tile >> 2, cib = tile & 3;
    int idx = blockIdx.x * 256 + threadIdx.x;   // 0..16383
    int n = idx >> 6, k = idx & 63;
    int ci = cib * 64 + k;
    float v = 0.f;
    if (n < 240 && ci < 240) v = fw[((size_t)n * FIN + ci) * 9 + s];
    __nv_bfloat16 hi = __float2bfloat16(v);
    __nv_bfloat16 lo = __float2bfloat16(v - __bfloat162float(hi));
    ((__nv_bfloat16*)(g_Wh4 + (size_t)tile * 2048))[idx] = hi;
    ((__nv_bfloat16*)(g_Wl4 + (size_t)tile * 2048))[idx] = lo;
}

// ================= HMMA conv kernel =================
// CTA = one (b, y) row: M=128 px, N=256 o. 512 threads = 16 warps, warp tile 32x64.
// K = 3 passes x 9 shifts x 4 ci-blocks of 64 = 108 chunks.
// Smem per buffer: A [128][72] bf16 (18432B) + B [256][72] bf16 (36864B) = 55296B; x2.
#define NCHUNK 108
#define ROWB   144               // padded row stride in bytes (72 bf16)
#define ABYTES (128 * ROWB)      // 18432
#define BUFSZ  (ABYTES + 256 * ROWB)  // 55296
#define CONV_SMEM (2 * BUFSZ)

__device__ __forceinline__ void load_chunk(int c, uint32_t sbuf, int t, int b, int y) {
    int pass = c / 36, rem = c % 36;
    int s = rem >> 2, cib = rem & 3;
    int dy = s / 3, dx = s % 3;
    const uint4* Xsrc = (pass == 1) ? g_Xl4 : g_Xh4;
    const uint4* Wsrc = ((pass == 2) ? g_Wl4 : g_Wh4) + (size_t)rem * 2048;

    int yy = y + dy - 1;
    bool yok = ((unsigned)yy < 128u);
    const uint4* xrow = Xsrc + (((size_t)b * 128 + (yok ? yy : 0)) * 128) * 32 + cib * 8;
    // A: 128 rows x 8 uint4 = 1024; 2 per thread
#pragma unroll
    for (int r = 0; r < 2; r++) {
        int i = t + r * 512;
        int m = i >> 3, j = i & 7;
        int xx = m + dx - 1;
        bool ok = yok && ((unsigned)xx < 128u);
        const uint4* src = xrow + (size_t)(ok ? xx : 0) * 32 + j;
        cpasync16(sbuf + m * ROWB + j * 16, src, ok ? 16u : 0u);
    }
    // B: 256 rows x 8 uint4 = 2048; 4 per thread
#pragma unroll
    for (int r = 0; r < 4; r++) {
        int i = t + r * 512;
        int n = i >> 3, j = i & 7;
        cpasync16(sbuf + ABYTES + n * ROWB + j * 16, Wsrc + n * 8 + j, 16u);
    }
    CP_COMMIT();
}

__global__ void __launch_bounds__(512, 1)
mma_conv_kernel(const float* __restrict__ fb, float* __restrict__ out) {
    extern __shared__ uint4 dsm[];
    uint32_t sb = smem_to_u32(dsm);

    int t = threadIdx.x;
    int l = t & 31, wid = t >> 5;
    int y = blockIdx.x, b = blockIdx.y;
    int m0 = (wid & 3) * 32;       // warp px base
    int n0 = (wid >> 2) * 64;      // warp out-ch base

    float acc[2][8][4];
#pragma unroll
    for (int i = 0; i < 2; i++)
#pragma unroll
        for (int j = 0; j < 8; j++)
#pragma unroll
            for (int k = 0; k < 4; k++) acc[i][j][k] = 0.f;

    // lane-derived ldmatrix base offsets (relative to buffer base)
    uint32_t aOff = (uint32_t)(m0 + (l & 15)) * ROWB + (l >> 4) * 16;
    uint32_t bOff = ABYTES + (uint32_t)(n0 + (l & 7) + ((l >> 4) << 3)) * ROWB
                    + ((l >> 3) & 1) * 16;

    load_chunk(0, sb, t, b, y);
    CP_WAIT0();
    __syncthreads();

    for (int c = 0; c < NCHUNK; c++) {
        uint32_t buf = sb + (c & 1) * BUFSZ;
        if (c + 1 < NCHUNK) load_chunk(c + 1, sb + ((c + 1) & 1) * BUFSZ, t, b, y);

        uint32_t aBase = buf + aOff;
        uint32_t bBase = buf + bOff;
#pragma unroll
        for (int ks = 0; ks < 4; ks++) {
            uint32_t a[2][4];
            ldsm4(a[0], aBase + ks * 32);
            ldsm4(a[1], aBase + 16 * ROWB + ks * 32);
            uint32_t bf[4][4];
#pragma unroll
            for (int nt = 0; nt < 4; nt++)
                ldsm4(bf[nt], bBase + nt * 16 * ROWB + ks * 32);
#pragma unroll
            for (int mt = 0; mt < 2; mt++)
#pragma unroll
                for (int nn = 0; nn < 8; nn++)
                    mma_bf16(acc[mt][nn], a[mt], &bf[nn >> 1][(nn & 1) * 2]);
        }
        if (c + 1 < NCHUNK) CP_WAIT0();
        __syncthreads();
    }

    // Epilogue: bias + factorized T contribution, scattered stores
    int g = l >> 2, tq = l & 3;
    float* outb = out + ((size_t)b * CC + 16) * (HH * WW) + y * WW;
#pragma unroll
    for (int mt = 0; mt < 2; mt++) {
        int xA = m0 + mt * 16 + g;
        int xB = xA + 8;
#pragma unroll
        for (int nn = 0; nn < 8; nn++) {
            int o0 = n0 + nn * 8 + 2 * tq;
            if (o0 >= 240) continue;
            float b0 = fb[o0], b1 = fb[o0 + 1];
#pragma unroll
            for (int half = 0; half < 2; half++) {
                int x = half ? xB : xA;
                float v0 = acc[mt][nn][half * 2 + 0] + b0;
                float v1 = acc[mt][nn][half * 2 + 1] + b1;
#pragma unroll
                for (int dy2 = 0; dy2 < 3; dy2++) {
                    int yy = y + dy2 - 1;
                    if ((unsigned)yy >= 128u) continue;
                    int hh = yy >> 1;
#pragma unroll
                    for (int dx2 = 0; dx2 < 3; dx2++) {
                        int xx = x + dx2 - 1;
                        if ((unsigned)xx >= 128u) continue;
                        int ww = xx >> 1;
                        float ev = g_e[b][hh][ww];
                        v0 += ev * g_G[b][o0][dy2 * 3 + dx2][ww];
                        v1 += ev * g_G[b][o0 + 1][dy2 * 3 + dx2][ww];
                    }
                }
                outb[(size_t)o0 * (HH * WW) + x] = v0;
                outb[(size_t)(o0 + 1) * (HH * WW) + x] = v1;
            }
        }
    }
}

// ---------------------------------------------------------------
extern "C" void kernel_launch(void* const* d_in, const int* in_sizes, int n_in,
                              void* d_out, int out_size) {
    const float* front = (const float*)d_in[0];
    const float* bev   = (const float*)d_in[1];
    const float* qw    = (const float*)d_in[2];
    const float* qb    = (const float*)d_in[3];
    const float* kw    = (const float*)d_in[4];
    const float* kb    = (const float*)d_in[5];
    const float* vw    = (const float*)d_in[6];
    const float* vb    = (const float*)d_in[7];
    const float* fw    = (const float*)d_in[8];
    const float* fb    = (const float*)d_in[9];
    float* out = (float*)d_out;

    static int smem_set = 0;
    if (!smem_set) {
        cudaFuncSetAttribute(mma_conv_kernel,
                             cudaFuncAttributeMaxDynamicSharedMemorySize, CONV_SMEM);
        smem_set = 1;
    }

    split_kernel<<<dim3(128, BB), 256>>>(bev);
    wbuild_kernel<<<dim3(64, 36), 256>>>(fw);
    front_reduce_kernel<<<dim3(CC, BB), 128>>>(front);
    bevpool_kernel<<<(BB * CC * HP * WP) / 256, 256>>>(bev);
    k_kernel<<<64, 256>>>(kw, kb);
    kq_kernel<<<512, 256>>>(qw, qb);
    e_kernel<<<dim3(HP, BB), WP>>>();
    enorm_kernel<<<dim3(WP, BB), HP>>>();
    vsum_kernel<<<dim3(32, BB), 64>>>(vw, vb);
    G_kernel<<<dim3(CE, BB), 64>>>(fw);
    copy16_kernel<<<2048, 256>>>(bev, out);
    mma_conv_kernel<<<dim3(128, BB), 512, CONV_SMEM>>>(fb, out);
}

// round 9
// speedup vs baseline: 2.9947x; 2.1483x over previous
#include <cuda_runtime.h>
#include <cuda_bf16.h>
#include <cuda_fp16.h>
#include <math.h>
#include <stdint.h>

// Problem constants
#define BB 8
#define CC 256
#define HH 128
#define WW 128
#define HP 64
#define WP 64
#define NC8 32
#define CE  240
#define FIN 496

// -------- scratch (device globals; no allocation allowed) --------
__device__ float g_A[3][BB][CC][WW];
__device__ float g_bevpool[BB][CC][HP][WP];
__device__ float g_k[BB][NC8][WP];
__device__ float g_kq[BB][CC][WP];
__device__ float g_kqb[BB][WP];
__device__ float g_e[BB][HP][WP];
__device__ float g_vs[BB][CC][WP];
__device__ float g_G[BB][CE][9][WP];

// channel-last fp16 input planes: [b][y][x][ci(256 padded)] ; 32 uint4 per pixel
__device__ uint4 g_X4[(size_t)BB * 128 * 128 * 32];
// weight tiles: 36 (9 shifts x 4 ci-blocks) x [n=256][k=64] fp16 row-major
__device__ uint4 g_W4[36 * 2048];

// ================= helpers =================
__device__ __forceinline__ uint32_t smem_to_u32(const void* p) {
    uint32_t a;
    asm("{ .reg .u64 t; cvta.to.shared.u64 t, %1; cvt.u32.u64 %0, t; }" : "=r"(a) : "l"(p));
    return a;
}
__device__ __forceinline__ void ldsm4(uint32_t* r, uint32_t addr) {
    asm volatile("ldmatrix.sync.aligned.m8n8.x4.shared.b16 {%0,%1,%2,%3}, [%4];"
                 : "=r"(r[0]), "=r"(r[1]), "=r"(r[2]), "=r"(r[3]) : "r"(addr));
}
__device__ __forceinline__ void mma_fp16(float* c, const uint32_t* a, const uint32_t* b) {
    asm volatile(
        "mma.sync.aligned.m16n8k16.row.col.f32.f16.f16.f32 "
        "{%0,%1,%2,%3}, {%4,%5,%6,%7}, {%8,%9}, {%0,%1,%2,%3};"
        : "+f"(c[0]), "+f"(c[1]), "+f"(c[2]), "+f"(c[3])
        : "r"(a[0]), "r"(a[1]), "r"(a[2]), "r"(a[3]), "r"(b[0]), "r"(b[1]));
}
__device__ __forceinline__ void cpasync16(uint32_t dst, const void* src, uint32_t sz) {
    asm volatile("cp.async.cg.shared.global [%0], [%1], 16, %2;"
                 :: "r"(dst), "l"(src), "r"(sz) : "memory");
}
#define CP_COMMIT() asm volatile("cp.async.commit_group;" ::: "memory")
#define CP_WAIT0()  asm volatile("cp.async.wait_group 0;" ::: "memory")

// ================= small kernels (validated) =================
__global__ void front_reduce_kernel(const float* __restrict__ fx) {
    int c = blockIdx.x, b = blockIdx.y, w = threadIdx.x;
    const float* p = fx + (((size_t)b * CC + c) * HH) * WW + w;
    float x0 = p[0];
    float xN = p[127 * WW];
    float s = 0.f;
#pragma unroll 8
    for (int h = 0; h < HH; h++) s += p[h * WW];
    g_A[0][b][c][w] = s - xN;
    g_A[1][b][c][w] = s;
    g_A[2][b][c][w] = s - x0;
}

__global__ void bevpool_kernel(const float* __restrict__ bev) {
    int idx = blockIdx.x * 256 + threadIdx.x;
    int w  = idx & 63;
    int h  = (idx >> 6) & 63;
    int bc = idx >> 12;
    const float2* r0 = (const float2*)(bev + ((size_t)bc * HH + 2 * h) * WW);
    const float2* r1 = (const float2*)(bev + ((size_t)bc * HH + 2 * h + 1) * WW);
    float2 a = r0[w], d = r1[w];
    ((float*)g_bevpool)[idx] = 0.25f * (a.x + a.y + d.x + d.y);
}

__global__ void k_kernel(const float* __restrict__ kw, const float* __restrict__ kb) {
    int tid = blockIdx.x * 256 + threadIdx.x;
    int w = tid & 63, o = (tid >> 6) & 31, b = tid >> 11;
    float acc = 0.f;
#pragma unroll 4
    for (int c = 0; c < CC; c++) {
        float m = (g_A[1][b][c][2 * w] + g_A[1][b][c][2 * w + 1]) * (1.f / 256.f);
        acc += kw[o * CC + c] * m;
    }
    g_k[b][o][w] = acc + kb[o];
}

__global__ void kq_kernel(const float* __restrict__ qw, const float* __restrict__ qb) {
    int tid = blockIdx.x * 256 + threadIdx.x;
    int w = tid & 63, c = (tid >> 6) & 255, b = tid >> 14;
    float acc = 0.f, accb = 0.f;
#pragma unroll 8
    for (int o = 0; o < NC8; o++) {
        float kk = g_k[b][o][w];
        acc  += kk * qw[o * CC + c];
        accb += kk * qb[o];
    }
    g_kq[b][c][w] = acc;
    if (c == 0) g_kqb[b][w] = accb;
}

__global__ void e_kernel() {
    int w = threadIdx.x, h = blockIdx.x, b = blockIdx.y;
    float acc = g_kqb[b][w];
#pragma unroll 4
    for (int c = 0; c < CC; c++)
        acc += g_kq[b][c][w] * g_bevpool[b][c][h][w];
    g_e[b][h][w] = acc;
}

__global__ void enorm_kernel() {
    int w = blockIdx.x, b = blockIdx.y, h = threadIdx.x;
    float v = g_e[b][h][w];
    float s = v * v;
#pragma unroll
    for (int off = 16; off; off >>= 1) s += __shfl_xor_sync(0xffffffffu, s, off);
    __shared__ float sh[2];
    if ((h & 31) == 0) sh[h >> 5] = s;
    __syncthreads();
    float tot = sh[0] + sh[1];
    g_e[b][h][w] = v * rsqrtf(tot);
}

__global__ void vsum_kernel(const float* __restrict__ vw, const float* __restrict__ vb) {
    __shared__ float sA[3][132];
    __shared__ float sW[8][9];
    int b = blockIdx.y, cg = blockIdx.x;
    int t = threadIdx.x;
    float acc[8];
#pragma unroll
    for (int j = 0; j < 8; j++) acc[j] = 0.f;

    for (int ci = 0; ci < CC; ci++) {
        __syncthreads();
        for (int i = t; i < 3 * 130; i += 64) {
            int arr = i / 130, u = i % 130;
            float v = 0.f;
            if (u >= 1 && u <= 128) v = g_A[arr][b][ci][u - 1];
            sA[arr][u] = v;
        }
        for (int i = t; i < 72; i += 64) {
            int j = i / 9, kk = i % 9;
            sW[j][kk] = vw[((size_t)(cg * 8 + j) * CC + ci) * 9 + kk];
        }
        __syncthreads();
#pragma unroll
        for (int sub = 0; sub < 2; sub++) {
            int wf = 2 * t + sub;
            float a[3][3];
#pragma unroll
            for (int dy = 0; dy < 3; dy++)
#pragma unroll
                for (int dx = 0; dx < 3; dx++) a[dy][dx] = sA[dy][wf + dx];
#pragma unroll
            for (int j = 0; j < 8; j++) {
                float s = acc[j];
#pragma unroll
                for (int dy = 0; dy < 3; dy++)
#pragma unroll
                    for (int dx = 0; dx < 3; dx++) s += sW[j][dy * 3 + dx] * a[dy][dx];
                acc[j] = s;
            }
        }
    }
#pragma unroll
    for (int j = 0; j < 8; j++)
        g_vs[b][cg * 8 + j][t] = 0.25f * acc[j] + 64.f * vb[cg * 8 + j];
}

__global__ void G_kernel(const float* __restrict__ fw) {
    int b = blockIdx.y, o = blockIdx.x, t = threadIdx.x;
    float acc[9];
#pragma unroll
    for (int j = 0; j < 9; j++) acc[j] = 0.f;
    for (int c = 0; c < CC; c++) {
        float v = g_vs[b][c][t];
        const float* wp = fw + ((size_t)o * FIN + 240 + c) * 9;
#pragma unroll
        for (int j = 0; j < 9; j++) acc[j] += wp[j] * v;
    }
#pragma unroll
    for (int j = 0; j < 9; j++) g_G[b][o][j][t] = acc[j];
}

__global__ void copy16_kernel(const float* __restrict__ bev, float* __restrict__ out) {
    int idx = blockIdx.x * 256 + threadIdx.x;
    int b = idx / (16 * 4096);
    int r = idx - b * (16 * 4096);
    size_t off = (size_t)b * (CC * 4096) + r;
    ((float4*)out)[off] = ((const float4*)bev)[off];
}

// ================= precompute kernels =================
// Split bev[:,16:] into channel-last fp16 planes (ci padded to 256 with zeros).
__global__ void __launch_bounds__(256) split_kernel(const float* __restrict__ bev) {
    __shared__ float sb[64][129];
    int y = blockIdx.x, b = blockIdx.y, t = threadIdx.x;
    for (int cb = 0; cb < 4; cb++) {
        __syncthreads();
        for (int i = t; i < 64 * 128; i += 256) {
            int ci = i >> 7, x = i & 127;
            int ch = cb * 64 + ci;
            float v = 0.f;
            if (ch < 240)
                v = bev[(((size_t)b * CC + 16 + ch) * HH + y) * WW + x];
            sb[ci][x] = v;
        }
        __syncthreads();
        for (int i = t; i < 128 * 32; i += 256) {
            int x = i >> 5, cp = i & 31;
            __half h0 = __float2half(sb[2 * cp][x]);
            __half h1 = __float2half(sb[2 * cp + 1][x]);
            uint32_t hp = ((uint32_t)__half_as_ushort(h1) << 16) | __half_as_ushort(h0);
            size_t base = (((size_t)b * 128 + y) * 128 + x) * 128 + cb * 32 + cp;
            ((uint32_t*)g_X4)[base] = hp;
        }
    }
}

// Weight tiles: tile (s, cib) = [n=256][k=64] fp16 row-major. grid (64, 36)
__global__ void wbuild_kernel(const float* __restrict__ fw) {
    int tile = blockIdx.y;
    int s = tile >> 2, cib = tile & 3;
    int idx = blockIdx.x * 256 + threadIdx.x;   // 0..16383
    int n = idx >> 6, k = idx & 63;
    int ci = cib * 64 + k;
    float v = 0.f;
    if (n < 240 && ci < 240) v = fw[((size_t)n * FIN + ci) * 9 + s];
    ((__half*)(g_W4 + (size_t)tile * 2048))[idx] = __float2half(v);
}

// ================= HMMA conv kernel =================
// CTA = one (b, y) row: M=128 px, N=256 o. 512 threads = 16 warps, warp tile 32x64.
// K = 9 shifts x 4 ci-blocks of 64 = 36 chunks (single fp16 pass).
#define NCHUNK 36
#define ROWB   144               // padded row stride in bytes (72 fp16)
#define ABYTES (128 * ROWB)      // 18432
#define BUFSZ  (ABYTES + 256 * ROWB)  // 55296
#define CONV_SMEM (2 * BUFSZ)

__device__ __forceinline__ void load_chunk(int c, uint32_t sbuf, int t, int b, int y) {
    int s = c >> 2, cib = c & 3;
    int dy = s / 3, dx = s % 3;
    const uint4* Wsrc = g_W4 + (size_t)c * 2048;

    int yy = y + dy - 1;
    bool yok = ((unsigned)yy < 128u);
    const uint4* xrow = g_X4 + (((size_t)b * 128 + (yok ? yy : 0)) * 128) * 32 + cib * 8;
    // A: 128 rows x 8 uint4 = 1024; 2 per thread
#pragma unroll
    for (int r = 0; r < 2; r++) {
        int i = t + r * 512;
        int m = i >> 3, j = i & 7;
        int xx = m + dx - 1;
        bool ok = yok && ((unsigned)xx < 128u);
        const uint4* src = xrow + (size_t)(ok ? xx : 0) * 32 + j;
        cpasync16(sbuf + m * ROWB + j * 16, src, ok ? 16u : 0u);
    }
    // B: 256 rows x 8 uint4 = 2048; 4 per thread
#pragma unroll
    for (int r = 0; r < 4; r++) {
        int i = t + r * 512;
        int n = i >> 3, j = i & 7;
        cpasync16(sbuf + ABYTES + n * ROWB + j * 16, Wsrc + n * 8 + j, 16u);
    }
    CP_COMMIT();
}

__global__ void __launch_bounds__(512, 1)
mma_conv_kernel(const float* __restrict__ fb, float* __restrict__ out) {
    extern __shared__ uint4 dsm[];
    uint32_t sb = smem_to_u32(dsm);

    int t = threadIdx.x;
    int l = t & 31, wid = t >> 5;
    int y = blockIdx.x, b = blockIdx.y;
    int m0 = (wid & 3) * 32;       // warp px base
    int n0 = (wid >> 2) * 64;      // warp out-ch base

    float acc[2][8][4];
#pragma unroll
    for (int i = 0; i < 2; i++)
#pragma unroll
        for (int j = 0; j < 8; j++)
#pragma unroll
            for (int k = 0; k < 4; k++) acc[i][j][k] = 0.f;

    uint32_t aOff = (uint32_t)(m0 + (l & 15)) * ROWB + (l >> 4) * 16;
    uint32_t bOff = ABYTES + (uint32_t)(n0 + (l & 7) + ((l >> 4) << 3)) * ROWB
                    + ((l >> 3) & 1) * 16;

    load_chunk(0, sb, t, b, y);
    CP_WAIT0();
    __syncthreads();

    for (int c = 0; c < NCHUNK; c++) {
        uint32_t buf = sb + (c & 1) * BUFSZ;
        if (c + 1 < NCHUNK) load_chunk(c + 1, sb + ((c + 1) & 1) * BUFSZ, t, b, y);

        uint32_t aBase = buf + aOff;
        uint32_t bBase = buf + bOff;
#pragma unroll
        for (int ks = 0; ks < 4; ks++) {
            uint32_t a[2][4];
            ldsm4(a[0], aBase + ks * 32);
            ldsm4(a[1], aBase + 16 * ROWB + ks * 32);
            uint32_t bf[4][4];
#pragma unroll
            for (int nt = 0; nt < 4; nt++)
                ldsm4(bf[nt], bBase + nt * 16 * ROWB + ks * 32);
#pragma unroll
            for (int mt = 0; mt < 2; mt++)
#pragma unroll
                for (int nn = 0; nn < 8; nn++)
                    mma_fp16(acc[mt][nn], a[mt], &bf[nn >> 1][(nn & 1) * 2]);
        }
        if (c + 1 < NCHUNK) CP_WAIT0();
        __syncthreads();
    }

    // Epilogue: bias + factorized T contribution, scattered stores
    int g = l >> 2, tq = l & 3;
    float* outb = out + ((size_t)b * CC + 16) * (HH * WW) + y * WW;
#pragma unroll
    for (int mt = 0; mt < 2; mt++) {
        int xA = m0 + mt * 16 + g;
        int xB = xA + 8;
#pragma unroll
        for (int nn = 0; nn < 8; nn++) {
            int o0 = n0 + nn * 8 + 2 * tq;
            if (o0 >= 240) continue;
            float b0 = fb[o0], b1 = fb[o0 + 1];
#pragma unroll
            for (int half = 0; half < 2; half++) {
                int x = half ? xB : xA;
                float v0 = acc[mt][nn][half * 2 + 0] + b0;
                float v1 = acc[mt][nn][half * 2 + 1] + b1;
#pragma unroll
                for (int dy2 = 0; dy2 < 3; dy2++) {
                    int yy = y + dy2 - 1;
                    if ((unsigned)yy >= 128u) continue;
                    int hh = yy >> 1;
#pragma unroll
                    for (int dx2 = 0; dx2 < 3; dx2++) {
                        int xx = x + dx2 - 1;
                        if ((unsigned)xx >= 128u) continue;
                        int ww = xx >> 1;
                        float ev = g_e[b][hh][ww];
                        v0 += ev * g_G[b][o0][dy2 * 3 + dx2][ww];
                        v1 += ev * g_G[b][o0 + 1][dy2 * 3 + dx2][ww];
                    }
                }
                outb[(size_t)o0 * (HH * WW) + x] = v0;
                outb[(size_t)(o0 + 1) * (HH * WW) + x] = v1;
            }
        }
    }
}

// ---------------------------------------------------------------
extern "C" void kernel_launch(void* const* d_in, const int* in_sizes, int n_in,
                              void* d_out, int out_size) {
    const float* front = (const float*)d_in[0];
    const float* bev   = (const float*)d_in[1];
    const float* qw    = (const float*)d_in[2];
    const float* qb    = (const float*)d_in[3];
    const float* kw    = (const float*)d_in[4];
    const float* kb    = (const float*)d_in[5];
    const float* vw    = (const float*)d_in[6];
    const float* vb    = (const float*)d_in[7];
    const float* fw    = (const float*)d_in[8];
    const float* fb    = (const float*)d_in[9];
    float* out = (float*)d_out;

    static int smem_set = 0;
    if (!smem_set) {
        cudaFuncSetAttribute(mma_conv_kernel,
                             cudaFuncAttributeMaxDynamicSharedMemorySize, CONV_SMEM);
        smem_set = 1;
    }

    split_kernel<<<dim3(128, BB), 256>>>(bev);
    wbuild_kernel<<<dim3(64, 36), 256>>>(fw);
    front_reduce_kernel<<<dim3(CC, BB), 128>>>(front);
    bevpool_kernel<<<(BB * CC * HP * WP) / 256, 256>>>(bev);
    k_kernel<<<64, 256>>>(kw, kb);
    kq_kernel<<<512, 256>>>(qw, qb);
    e_kernel<<<dim3(HP, BB), WP>>>();
    enorm_kernel<<<dim3(WP, BB), HP>>>();
    vsum_kernel<<<dim3(32, BB), 64>>>(vw, vb);
    G_kernel<<<dim3(CE, BB), 64>>>(fw);
    copy16_kernel<<<2048, 256>>>(bev, out);
    mma_conv_kernel<<<dim3(128, BB), 512, CONV_SMEM>>>(fb, out);
}

// round 10
// speedup vs baseline: 4.4874x; 1.4984x over previous
#include <cuda_runtime.h>
#include <cuda_bf16.h>
#include <cuda_fp16.h>
#include <math.h>
#include <stdint.h>

// Problem constants
#define BB 8
#define CC 256
#define HH 128
#define WW 128
#define HP 64
#define WP 64
#define NC8 32
#define CE  240
#define FIN 496

// -------- scratch (device globals; no allocation allowed) --------
__device__ float g_A[3][BB][CC][WW];
__device__ float g_bevpool[BB][CC][HP][WP];
__device__ float g_k[BB][NC8][WP];
__device__ float g_kq[BB][CC][WP];
__device__ float g_kqb[BB][WP];
__device__ float g_e[BB][HP][WP];
__device__ float g_vs[BB][CC][WP];
__device__ float g_G[BB][CE][9][WP];

// channel-last fp16 input planes: [b][y][x][ci(256 padded)] ; 32 uint4 per pixel
__device__ uint4 g_X4[(size_t)BB * 128 * 128 * 32];
// weight tiles: 36 (9 shifts x 4 ci-blocks) x [n=256][k=64] fp16 row-major
__device__ uint4 g_W4[36 * 2048];

// ================= helpers =================
__device__ __forceinline__ uint32_t smem_to_u32(const void* p) {
    uint32_t a;
    asm("{ .reg .u64 t; cvta.to.shared.u64 t, %1; cvt.u32.u64 %0, t; }" : "=r"(a) : "l"(p));
    return a;
}
__device__ __forceinline__ void ldsm4(uint32_t* r, uint32_t addr) {
    asm volatile("ldmatrix.sync.aligned.m8n8.x4.shared.b16 {%0,%1,%2,%3}, [%4];"
                 : "=r"(r[0]), "=r"(r[1]), "=r"(r[2]), "=r"(r[3]) : "r"(addr));
}
__device__ __forceinline__ void mma_fp16(float* c, const uint32_t* a, const uint32_t* b) {
    asm volatile(
        "mma.sync.aligned.m16n8k16.row.col.f32.f16.f16.f32 "
        "{%0,%1,%2,%3}, {%4,%5,%6,%7}, {%8,%9}, {%0,%1,%2,%3};"
        : "+f"(c[0]), "+f"(c[1]), "+f"(c[2]), "+f"(c[3])
        : "r"(a[0]), "r"(a[1]), "r"(a[2]), "r"(a[3]), "r"(b[0]), "r"(b[1]));
}
__device__ __forceinline__ void cpasync16(uint32_t dst, const void* src, uint32_t sz) {
    asm volatile("cp.async.cg.shared.global [%0], [%1], 16, %2;"
                 :: "r"(dst), "l"(src), "r"(sz) : "memory");
}
#define CP_COMMIT() asm volatile("cp.async.commit_group;" ::: "memory")
#define CP_WAIT0()  asm volatile("cp.async.wait_group 0;" ::: "memory")

// ================= small kernels =================
__global__ void front_reduce_kernel(const float* __restrict__ fx) {
    int c = blockIdx.x, b = blockIdx.y, w = threadIdx.x;
    const float* p = fx + (((size_t)b * CC + c) * HH) * WW + w;
    float x0 = p[0];
    float xN = p[127 * WW];
    float s = 0.f;
#pragma unroll 8
    for (int h = 0; h < HH; h++) s += p[h * WW];
    g_A[0][b][c][w] = s - xN;
    g_A[1][b][c][w] = s;
    g_A[2][b][c][w] = s - x0;
}

__global__ void bevpool_kernel(const float* __restrict__ bev) {
    int idx = blockIdx.x * 256 + threadIdx.x;
    int w  = idx & 63;
    int h  = (idx >> 6) & 63;
    int bc = idx >> 12;
    const float2* r0 = (const float2*)(bev + ((size_t)bc * HH + 2 * h) * WW);
    const float2* r1 = (const float2*)(bev + ((size_t)bc * HH + 2 * h + 1) * WW);
    float2 a = r0[w], d = r1[w];
    ((float*)g_bevpool)[idx] = 0.25f * (a.x + a.y + d.x + d.y);
}

__global__ void k_kernel(const float* __restrict__ kw, const float* __restrict__ kb) {
    int tid = blockIdx.x * 256 + threadIdx.x;
    int w = tid & 63, o = (tid >> 6) & 31, b = tid >> 11;
    float acc = 0.f;
#pragma unroll 4
    for (int c = 0; c < CC; c++) {
        float m = (g_A[1][b][c][2 * w] + g_A[1][b][c][2 * w + 1]) * (1.f / 256.f);
        acc += kw[o * CC + c] * m;
    }
    g_k[b][o][w] = acc + kb[o];
}

__global__ void kq_kernel(const float* __restrict__ qw, const float* __restrict__ qb) {
    int tid = blockIdx.x * 256 + threadIdx.x;
    int w = tid & 63, c = (tid >> 6) & 255, b = tid >> 14;
    float acc = 0.f, accb = 0.f;
#pragma unroll 8
    for (int o = 0; o < NC8; o++) {
        float kk = g_k[b][o][w];
        acc  += kk * qw[o * CC + c];
        accb += kk * qb[o];
    }
    g_kq[b][c][w] = acc;
    if (c == 0) g_kqb[b][w] = accb;
}

__global__ void e_kernel() {
    int w = threadIdx.x, h = blockIdx.x, b = blockIdx.y;
    float acc = g_kqb[b][w];
#pragma unroll 4
    for (int c = 0; c < CC; c++)
        acc += g_kq[b][c][w] * g_bevpool[b][c][h][w];
    g_e[b][h][w] = acc;
}

__global__ void enorm_kernel() {
    int w = blockIdx.x, b = blockIdx.y, h = threadIdx.x;
    float v = g_e[b][h][w];
    float s = v * v;
#pragma unroll
    for (int off = 16; off; off >>= 1) s += __shfl_xor_sync(0xffffffffu, s, off);
    __shared__ float sh[2];
    if ((h & 31) == 0) sh[h >> 5] = s;
    __syncthreads();
    float tot = sh[0] + sh[1];
    g_e[b][h][w] = v * rsqrtf(tot);
}

// vsum: 4-way c-parallel. grid (32 cg, 8 b), block 256 = 4 c-subgroups x 64 w'
__global__ void __launch_bounds__(256) vsum_kernel(const float* __restrict__ vw,
                                                   const float* __restrict__ vb) {
    __shared__ float sA[4][3][132];
    __shared__ float sW[4][8][9];
    __shared__ float sred[4][8][64];
    int b = blockIdx.y, cg = blockIdx.x;
    int t = threadIdx.x;
    int grp = t >> 6, w = t & 63;
    float acc[8];
#pragma unroll
    for (int j = 0; j < 8; j++) acc[j] = 0.f;

    for (int k = 0; k < 64; k++) {
        int ci = 4 * k + grp;
        __syncthreads();
        for (int i = w; i < 390; i += 64) {
            int arr = i / 130, u = i % 130;
            float v = 0.f;
            if (u >= 1 && u <= 128) v = g_A[arr][b][ci][u - 1];
            sA[grp][arr][u] = v;
        }
        for (int i = w; i < 72; i += 64) {
            int j = i / 9, kk = i % 9;
            sW[grp][j][kk] = vw[((size_t)(cg * 8 + j) * CC + ci) * 9 + kk];
        }
        __syncthreads();
#pragma unroll
        for (int sub = 0; sub < 2; sub++) {
            int wf = 2 * w + sub;
            float a[3][3];
#pragma unroll
            for (int dy = 0; dy < 3; dy++)
#pragma unroll
                for (int dx = 0; dx < 3; dx++) a[dy][dx] = sA[grp][dy][wf + dx];
#pragma unroll
            for (int j = 0; j < 8; j++) {
                float s = acc[j];
#pragma unroll
                for (int dy = 0; dy < 3; dy++)
#pragma unroll
                    for (int dx = 0; dx < 3; dx++) s += sW[grp][j][dy * 3 + dx] * a[dy][dx];
                acc[j] = s;
            }
        }
    }
    __syncthreads();
#pragma unroll
    for (int j = 0; j < 8; j++) sred[grp][j][w] = acc[j];
    __syncthreads();
    if (grp == 0) {
#pragma unroll
        for (int j = 0; j < 8; j++) {
            float tot = sred[0][j][w] + sred[1][j][w] + sred[2][j][w] + sred[3][j][w];
            g_vs[b][cg * 8 + j][w] = 0.25f * tot + 64.f * vb[cg * 8 + j];
        }
    }
}

// G: stage contiguous 2304-float weight block in smem. grid (CE, BB), 64 threads
__global__ void G_kernel(const float* __restrict__ fw) {
    __shared__ float sw[2304];
    int b = blockIdx.y, o = blockIdx.x, t = threadIdx.x;
    const float* wbase = fw + ((size_t)o * FIN + 240) * 9;
    for (int i = t; i < 2304; i += 64) sw[i] = wbase[i];
    __syncthreads();
    float acc[9];
#pragma unroll
    for (int j = 0; j < 9; j++) acc[j] = 0.f;
    for (int c = 0; c < CC; c++) {
        float v = g_vs[b][c][t];
#pragma unroll
        for (int j = 0; j < 9; j++) acc[j] += sw[c * 9 + j] * v;
    }
#pragma unroll
    for (int j = 0; j < 9; j++) g_G[b][o][j][t] = acc[j];
}

__global__ void copy16_kernel(const float* __restrict__ bev, float* __restrict__ out) {
    int idx = blockIdx.x * 256 + threadIdx.x;
    int b = idx / (16 * 4096);
    int r = idx - b * (16 * 4096);
    size_t off = (size_t)b * (CC * 4096) + r;
    ((float4*)out)[off] = ((const float4*)bev)[off];
}

// ================= precompute kernels =================
__global__ void __launch_bounds__(256) split_kernel(const float* __restrict__ bev) {
    __shared__ float sb[64][129];
    int y = blockIdx.x, b = blockIdx.y, t = threadIdx.x;
    for (int cb = 0; cb < 4; cb++) {
        __syncthreads();
        for (int i = t; i < 64 * 128; i += 256) {
            int ci = i >> 7, x = i & 127;
            int ch = cb * 64 + ci;
            float v = 0.f;
            if (ch < 240)
                v = bev[(((size_t)b * CC + 16 + ch) * HH + y) * WW + x];
            sb[ci][x] = v;
        }
        __syncthreads();
        for (int i = t; i < 128 * 32; i += 256) {
            int x = i >> 5, cp = i & 31;
            __half h0 = __float2half(sb[2 * cp][x]);
            __half h1 = __float2half(sb[2 * cp + 1][x]);
            uint32_t hp = ((uint32_t)__half_as_ushort(h1) << 16) | __half_as_ushort(h0);
            size_t base = (((size_t)b * 128 + y) * 128 + x) * 128 + cb * 32 + cp;
            ((uint32_t*)g_X4)[base] = hp;
        }
    }
}

__global__ void wbuild_kernel(const float* __restrict__ fw) {
    int tile = blockIdx.y;
    int s = tile >> 2, cib = tile & 3;
    int idx = blockIdx.x * 256 + threadIdx.x;
    int n = idx >> 6, k = idx & 63;
    int ci = cib * 64 + k;
    float v = 0.f;
    if (n < 240 && ci < 240) v = fw[((size_t)n * FIN + ci) * 9 + s];
    ((__half*)(g_W4 + (size_t)tile * 2048))[idx] = __float2half(v);
}

// ================= HMMA conv kernel =================
#define NCHUNK 36
#define ROWB   144
#define ABYTES (128 * ROWB)
#define BUFSZ  (ABYTES + 256 * ROWB)
#define CONV_SMEM (2 * BUFSZ)

__device__ __forceinline__ void load_chunk(int c, uint32_t sbuf, int t, int b, int y) {
    int s = c >> 2, cib = c & 3;
    int dy = s / 3, dx = s % 3;
    const uint4* Wsrc = g_W4 + (size_t)c * 2048;

    int yy = y + dy - 1;
    bool yok = ((unsigned)yy < 128u);
    const uint4* xrow = g_X4 + (((size_t)b * 128 + (yok ? yy : 0)) * 128) * 32 + cib * 8;
#pragma unroll
    for (int r = 0; r < 2; r++) {
        int i = t + r * 512;
        int m = i >> 3, j = i & 7;
        int xx = m + dx - 1;
        bool ok = yok && ((unsigned)xx < 128u);
        const uint4* src = xrow + (size_t)(ok ? xx : 0) * 32 + j;
        cpasync16(sbuf + m * ROWB + j * 16, src, ok ? 16u : 0u);
    }
#pragma unroll
    for (int r = 0; r < 4; r++) {
        int i = t + r * 512;
        int n = i >> 3, j = i & 7;
        cpasync16(sbuf + ABYTES + n * ROWB + j * 16, Wsrc + n * 8 + j, 16u);
    }
    CP_COMMIT();
}

__device__ __forceinline__ void do_ks(int ks, uint32_t aBase, uint32_t bBase,
                                      float acc[2][8][4], int ntMax, int nnMax) {
    uint32_t a[2][4];
    ldsm4(a[0], aBase + ks * 32);
    ldsm4(a[1], aBase + 16 * ROWB + ks * 32);
    uint32_t bf[4][4];
#pragma unroll
    for (int nt = 0; nt < 4; nt++)
        if (nt < ntMax) ldsm4(bf[nt], bBase + nt * 16 * ROWB + ks * 32);
#pragma unroll
    for (int mt = 0; mt < 2; mt++)
#pragma unroll
        for (int nn = 0; nn < 8; nn++)
            if (nn < nnMax) mma_fp16(acc[mt][nn], a[mt], &bf[nn >> 1][(nn & 1) * 2]);
}

__global__ void __launch_bounds__(512, 1)
mma_conv_kernel(const float* __restrict__ fb, float* __restrict__ out) {
    extern __shared__ uint4 dsm[];
    uint32_t sb = smem_to_u32(dsm);

    int t = threadIdx.x;
    int l = t & 31, wid = t >> 5;
    int y = blockIdx.x, b = blockIdx.y;
    int m0 = (wid & 3) * 32;
    int n0 = (wid >> 2) * 64;
    // warp-uniform trims: outputs 240..255 are discarded
    const int nnMax = (n0 == 192) ? 6 : 8;
    const int ntMax = (n0 == 192) ? 3 : 4;

    float acc[2][8][4];
#pragma unroll
    for (int i = 0; i < 2; i++)
#pragma unroll
        for (int j = 0; j < 8; j++)
#pragma unroll
            for (int k = 0; k < 4; k++) acc[i][j][k] = 0.f;

    uint32_t aOff = (uint32_t)(m0 + (l & 15)) * ROWB + (l >> 4) * 16;
    uint32_t bOff = ABYTES + (uint32_t)(n0 + (l & 7) + ((l >> 4) << 3)) * ROWB
                    + ((l >> 3) & 1) * 16;

    load_chunk(0, sb, t, b, y);
    CP_WAIT0();
    __syncthreads();

    for (int c = 0; c < NCHUNK; c++) {
        uint32_t buf = sb + (c & 1) * BUFSZ;
        if (c + 1 < NCHUNK) load_chunk(c + 1, sb + ((c + 1) & 1) * BUFSZ, t, b, y);

        uint32_t aBase = buf + aOff;
        uint32_t bBase = buf + bOff;
        // cib==3 covers ci 192..255; 240..255 are zero padding -> skip ks=3
        int ksMax = ((c & 3) == 3) ? 3 : 4;
#pragma unroll
        for (int ks = 0; ks < 4; ks++)
            if (ks < ksMax) do_ks(ks, aBase, bBase, acc, ntMax, nnMax);

        if (c + 1 < NCHUNK) CP_WAIT0();
        __syncthreads();
    }

    // Epilogue: bias + factorized T contribution, scattered stores
    int g = l >> 2, tq = l & 3;
    float* outb = out + ((size_t)b * CC + 16) * (HH * WW) + y * WW;
#pragma unroll
    for (int mt = 0; mt < 2; mt++) {
        int xA = m0 + mt * 16 + g;
        int xB = xA + 8;
#pragma unroll
        for (int nn = 0; nn < 8; nn++) {
            int o0 = n0 + nn * 8 + 2 * tq;
            if (o0 >= 240) continue;
            float b0 = fb[o0], b1 = fb[o0 + 1];
#pragma unroll
            for (int half = 0; half < 2; half++) {
                int x = half ? xB : xA;
                float v0 = acc[mt][nn][half * 2 + 0] + b0;
                float v1 = acc[mt][nn][half * 2 + 1] + b1;
#pragma unroll
                for (int dy2 = 0; dy2 < 3; dy2++) {
                    int yy = y + dy2 - 1;
                    if ((unsigned)yy >= 128u) continue;
                    int hh = yy >> 1;
#pragma unroll
                    for (int dx2 = 0; dx2 < 3; dx2++) {
                        int xx = x + dx2 - 1;
                        if ((unsigned)xx >= 128u) continue;
                        int ww = xx >> 1;
                        float ev = g_e[b][hh][ww];
                        v0 += ev * g_G[b][o0][dy2 * 3 + dx2][ww];
                        v1 += ev * g_G[b][o0 + 1][dy2 * 3 + dx2][ww];
                    }
                }
                outb[(size_t)o0 * (HH * WW) + x] = v0;
                outb[(size_t)(o0 + 1) * (HH * WW) + x] = v1;
            }
        }
    }
}

// ---------------------------------------------------------------
extern "C" void kernel_launch(void* const* d_in, const int* in_sizes, int n_in,
                              void* d_out, int out_size) {
    const float* front = (const float*)d_in[0];
    const float* bev   = (const float*)d_in[1];
    const float* qw    = (const float*)d_in[2];
    const float* qb    = (const float*)d_in[3];
    const float* kw    = (const float*)d_in[4];
    const float* kb    = (const float*)d_in[5];
    const float* vw    = (const float*)d_in[6];
    const float* vb    = (const float*)d_in[7];
    const float* fw    = (const float*)d_in[8];
    const float* fb    = (const float*)d_in[9];
    float* out = (float*)d_out;

    cudaFuncSetAttribute(mma_conv_kernel,
                         cudaFuncAttributeMaxDynamicSharedMemorySize, CONV_SMEM);

    split_kernel<<<dim3(128, BB), 256>>>(bev);
    wbuild_kernel<<<dim3(64, 36), 256>>>(fw);
    front_reduce_kernel<<<dim3(CC, BB), 128>>>(front);
    bevpool_kernel<<<(BB * CC * HP * WP) / 256, 256>>>(bev);
    k_kernel<<<64, 256>>>(kw, kb);
    kq_kernel<<<512, 256>>>(qw, qb);
    e_kernel<<<dim3(HP, BB), WP>>>();
    enorm_kernel<<<dim3(WP, BB), HP>>>();
    vsum_kernel<<<dim3(32, BB), 256>>>(vw, vb);
    G_kernel<<<dim3(CE, BB), 64>>>(fw);
    copy16_kernel<<<2048, 256>>>(bev, out);
    mma_conv_kernel<<<dim3(128, BB), 512, CONV_SMEM>>>(fb, out);
}